// round 4
// baseline (speedup 1.0000x reference)
#include <cuda_runtime.h>
#include <cstdint>

// ---------- MUFU helpers ----------
__device__ __forceinline__ float fex2(float x) {
    float r; asm("ex2.approx.f32 %0, %1;" : "=f"(r) : "f"(x)); return r;
}
__device__ __forceinline__ float frcp(float x) {
    float r; asm("rcp.approx.f32 %0, %1;" : "=f"(r) : "f"(x)); return r;
}
__device__ __forceinline__ float ftanha(float x) {
    float r; asm("tanh.approx.f32 %0, %1;" : "=f"(r) : "f"(x)); return r;
}
__device__ __forceinline__ float fsig_exact(float x) {
    return frcp(1.0f + fex2(-1.44269504f * x));
}
__device__ __forceinline__ float ftanh_exact(float x) {
    return fmaf(-2.0f, frcp(1.0f + fex2(2.88539008f * x)), 1.0f);
}

// ---------- problem constants ----------
constexpr int BATCH = 8192;
constexpr int HID   = 10;
constexpr int STEPS = 512;
constexpr int WPB   = 10;
constexpr int TPB   = WPB * 32;        // 320
constexpr int GRID  = 296;             // exactly 2 blocks per SM
constexpr int TOTW  = GRID * WPB;      // 2960 warps; elem e_i = g + i*2960
constexpr int HPAD  = 12;              // padded h row (floats) for LDS.128

// Folded weights: G = w_ih @ l2_w @ l1_w (30x10), d = w_ih@l2_b + (w_ih@l2_w)@l1_b + b_ih (30)
__device__ float g_G[300];
__device__ float g_d[30];
// sink rows for lanes without a valid batch element (branch-free stores)
__device__ float g_sink[STEPS * HID];

// ---------- prep kernel: fold the input path ----------
__global__ void prep_kernel(const float* __restrict__ w_ih,
                            const float* __restrict__ b_ih,
                            const float* __restrict__ l1_w,
                            const float* __restrict__ l1_b,
                            const float* __restrict__ l2_w,
                            const float* __restrict__ l2_b) {
    __shared__ float Wm[300]; // w_ih @ l2_w : (30,10)
    int t = threadIdx.x;
    if (t < 300) {
        int r = t / 10, m = t % 10;
        float s = 0.0f;
        for (int i = 0; i < 64; i++) s += w_ih[r * 64 + i] * l2_w[i * 10 + m];
        Wm[t] = s;
    }
    __syncthreads();
    if (t < 300) {
        int r = t / 10, k = t % 10;
        float g = 0.0f;
        for (int m = 0; m < 10; m++) g += Wm[r * 10 + m] * l1_w[m * 10 + k];
        g_G[t] = g;
    } else if (t < 330) {
        int r = t - 300;
        float s = b_ih[r];
        for (int i = 0; i < 64; i++) s += w_ih[r * 64 + i] * l2_b[i];
        for (int m = 0; m < 10; m++) s += Wm[r * 10 + m] * l1_b[m];
        g_d[r] = s;
    }
}

// ---------- main recurrence kernel ----------
// thread = (batch element, gate dim j). 3 elements per warp on lanes 0..29;
// lanes 30/31 shadow element-group 0 (identical stream, stores to sink).
// Scalar fp32 math, 2731 active warps (~20/SM) for latency hiding.
// h exchanged through a warp-local double-buffered shared row (LDS.128
// broadcast reads); one __syncwarp per step.
// All three activations via tanh.approx (sigma(a)=0.5+0.5*tanh(a/2), the 0.5
// folded into r/z weights).
__global__ void __launch_bounds__(TPB, 2) gru_kernel(
    const float* __restrict__ hidden,
    const float* __restrict__ w_hh,
    const float* __restrict__ b_ih,
    const float* __restrict__ b_hh,
    const float* __restrict__ l1_w,
    const float* __restrict__ l1_b,
    float* __restrict__ out) {
    __shared__ alignas(16) float hsh[WPB][2][3][HPAD];

    const int lane = threadIdx.x & 31;
    const int w    = threadIdx.x >> 5;
    const int p    = lane / 10;            // 0..2 element slot, 3 = spare lanes
    const int e    = (p < 3) ? p : 0;      // spare lanes shadow element 0
    const int j    = lane - p * 10;        // 0..9 (spares: 0..1)
    const int g    = blockIdx.x * WPB + w;
    const int eIdx = g + e * TOTW;         // round-robin element map
    const bool valid = (p < 3) && (eIdx < BATCH);

    // per-thread folded + scaled weight rows (scalar)
    float Mr[10], Mz[10], Gn[10], Wn[10], L1[10];
#pragma unroll
    for (int k = 0; k < 10; k++) {
        Mr[k] = 0.5f * (w_hh[j * 10 + k]        + g_G[j * 10 + k]);
        Mz[k] = 0.5f * (w_hh[(10 + j) * 10 + k] + g_G[(10 + j) * 10 + k]);
        Gn[k] = g_G[(20 + j) * 10 + k];
        Wn[k] = w_hh[(20 + j) * 10 + k];
        L1[k] = l1_w[j * 10 + k];
    }
    const float vbr  = 0.5f * (b_hh[j]      + g_d[j]);
    const float vbz  = 0.5f * (b_hh[10 + j] + g_d[10 + j]);
    const float vbin = g_d[20 + j];
    const float vbhn = b_hh[20 + j];
    const float vl1b = l1_b[j];

    const int eLoad = valid ? eIdx : (g < BATCH ? g : 0);
    float h = hidden[eLoad * 10 + j];

    hsh[w][0][e][j] = h;
    __syncwarp();

    // peeled step 0: x0 = 0 -> gi = b_ih exactly (no G*h term). Exact activations.
    {
        float aR = b_hh[j] + b_ih[j];
        float aZ = b_hh[10 + j] + b_ih[10 + j];
        float aH = b_hh[20 + j];
#pragma unroll
        for (int k = 0; k < 10; k++) {
            float hk = hsh[w][0][e][k];
            aR = fmaf(w_hh[j * 10 + k], hk, aR);
            aZ = fmaf(w_hh[(10 + j) * 10 + k], hk, aZ);
            aH = fmaf(w_hh[(20 + j) * 10 + k], hk, aH);
        }
        float r = fsig_exact(aR);
        float z = fsig_exact(aZ);
        float n = ftanh_exact(fmaf(r, aH, b_ih[20 + j]));
        h = fmaf(z, h - n, n);
    }
    hsh[w][1][e][j] = h;

    // REVERSE output: o_t -> row (511 - t); at iter t we emit o_{t-1} -> row 512 - t
    float* o = valid
        ? out + (size_t)eIdx * (STEPS * HID) + (STEPS - 1) * HID + j
        : g_sink + (STEPS - 1) * HID + j;

#pragma unroll 2
    for (int t = 1; t < STEPS; ++t) {
        __syncwarp();
        const int rb = t & 1;
        const float* hp = &hsh[w][rb][e][0];
        const float4 h03 = *reinterpret_cast<const float4*>(hp);
        const float4 h47 = *reinterpret_cast<const float4*>(hp + 4);
        const float2 h89 = *reinterpret_cast<const float2*>(hp + 8);
        float hk[10] = {h03.x, h03.y, h03.z, h03.w,
                        h47.x, h47.y, h47.z, h47.w,
                        h89.x, h89.y};

        // split accumulator chains (5 deep each) for all five dots
        float aR = vbr,  aR2 = 0.0f;
        float aZ = vbz,  aZ2 = 0.0f;
        float aI = vbin, aI2 = 0.0f;
        float aH = vbhn, aH2 = 0.0f;
        float aO = vl1b, aO2 = 0.0f;
#pragma unroll
        for (int k = 0; k < 10; k += 2) {
            aR  = fmaf(Mr[k], hk[k], aR);   aR2 = fmaf(Mr[k + 1], hk[k + 1], aR2);
            aH  = fmaf(Wn[k], hk[k], aH);   aH2 = fmaf(Wn[k + 1], hk[k + 1], aH2);
            aZ  = fmaf(Mz[k], hk[k], aZ);   aZ2 = fmaf(Mz[k + 1], hk[k + 1], aZ2);
            aI  = fmaf(Gn[k], hk[k], aI);   aI2 = fmaf(Gn[k + 1], hk[k + 1], aI2);
            aO  = fmaf(L1[k], hk[k], aO);   aO2 = fmaf(L1[k + 1], hk[k + 1], aO2);
        }
        aR += aR2; aH += aH2; aZ += aZ2; aI += aI2;

        // store o_{t-1} (computed from h_t = h_new of step t-1)
        *o = aO + aO2;
        o -= HID;

        // r = 0.5 + 0.5*tanh(aR), z likewise (pre-scaled by 0.5)
        float r = fmaf(0.5f, ftanha(aR), 0.5f);
        float z = fmaf(0.5f, ftanha(aZ), 0.5f);
        // n = tanh(aI + r*aH)
        float n = ftanha(fmaf(r, aH, aI));
        // h' = n + z*(h - n)
        h = fmaf(z, h - n, n);
        hsh[w][rb ^ 1][e][j] = h;
    }

    // epilogue: o_511 -> row 0 (h_512 sits in buffer 0 after t=511)
    __syncwarp();
    {
        float aO = vl1b, aO2 = 0.0f;
        const float* hp = &hsh[w][0][e][0];
#pragma unroll
        for (int k = 0; k < 10; k += 2) {
            aO  = fmaf(L1[k], hp[k], aO);
            aO2 = fmaf(L1[k + 1], hp[k + 1], aO2);
        }
        *o = aO + aO2;
    }
}

extern "C" void kernel_launch(void* const* d_in, const int* in_sizes, int n_in,
                              void* d_out, int out_size) {
    const float* hidden = (const float*)d_in[0];
    const float* w_ih   = (const float*)d_in[1];
    const float* w_hh   = (const float*)d_in[2];
    const float* b_ih   = (const float*)d_in[3];
    const float* b_hh   = (const float*)d_in[4];
    const float* l1_w   = (const float*)d_in[5];
    const float* l1_b   = (const float*)d_in[6];
    const float* l2_w   = (const float*)d_in[7];
    const float* l2_b   = (const float*)d_in[8];

    prep_kernel<<<1, 384>>>(w_ih, b_ih, l1_w, l1_b, l2_w, l2_b);
    gru_kernel<<<GRID, TPB>>>(hidden, w_hh, b_ih, b_hh, l1_w, l1_b, (float*)d_out);
}

// round 5
// speedup vs baseline: 1.1676x; 1.1676x over previous
#include <cuda_runtime.h>
#include <cstdint>

typedef unsigned long long u64;

// ---------- f32x2 / MUFU helpers ----------
__device__ __forceinline__ u64 ffma2(u64 a, u64 b, u64 c) {
    u64 d;
    asm("fma.rn.f32x2 %0, %1, %2, %3;" : "=l"(d) : "l"(a), "l"(b), "l"(c));
    return d;
}
__device__ __forceinline__ u64 fadd2(u64 a, u64 b) {
    u64 d;
    asm("add.rn.f32x2 %0, %1, %2;" : "=l"(d) : "l"(a), "l"(b));
    return d;
}
__device__ __forceinline__ u64 fpack(float x, float y) {
    u64 d;
    asm("mov.b64 %0, {%1, %2};" : "=l"(d) : "r"(__float_as_uint(x)), "r"(__float_as_uint(y)));
    return d;
}
__device__ __forceinline__ u64 fdup(float s) { return fpack(s, s); }
__device__ __forceinline__ void funpack(u64 v, float& x, float& y) {
    unsigned int a, b;
    asm("mov.b64 {%0, %1}, %2;" : "=r"(a), "=r"(b) : "l"(v));
    x = __uint_as_float(a);
    y = __uint_as_float(b);
}
__device__ __forceinline__ float fex2(float x) {
    float r; asm("ex2.approx.f32 %0, %1;" : "=f"(r) : "f"(x)); return r;
}
__device__ __forceinline__ float frcp(float x) {
    float r; asm("rcp.approx.f32 %0, %1;" : "=f"(r) : "f"(x)); return r;
}
__device__ __forceinline__ float ftanha(float x) {
    float r; asm("tanh.approx.f32 %0, %1;" : "=f"(r) : "f"(x)); return r;
}
__device__ __forceinline__ float fsig_exact(float x) {
    return frcp(1.0f + fex2(-1.44269504f * x));
}
__device__ __forceinline__ float ftanh_exact(float x) {
    return fmaf(-2.0f, frcp(1.0f + fex2(2.88539008f * x)), 1.0f);
}

// ---------- problem constants ----------
constexpr int BATCH = 8192;
constexpr int HID   = 10;
constexpr int STEPS = 512;
constexpr int DUOS  = BATCH / 4;       // 2048 duos; 1 duo = 2 f32x2 pairs = 4 elements
constexpr int WPB   = 5;
constexpr int TPB   = WPB * 32;        // 160
constexpr int GRID  = 148;             // exactly 1 block / SM, 5 warps each
constexpr int TOTW  = GRID * WPB;      // 740 warps; duo slot s of warp g -> duo g + s*740

// Folded weights: G = w_ih @ l2_w @ l1_w (30x10), d = w_ih@l2_b + (w_ih@l2_w)@l1_b + b_ih (30)
__device__ float g_G[300];
__device__ float g_d[30];
// sink region for threads without a valid duo (branch-free stores, dec=0)
__device__ float g_sink[8192 + 64];

// ---------- prep kernel: fold the input path ----------
__global__ void prep_kernel(const float* __restrict__ w_ih,
                            const float* __restrict__ b_ih,
                            const float* __restrict__ l1_w,
                            const float* __restrict__ l1_b,
                            const float* __restrict__ l2_w,
                            const float* __restrict__ l2_b) {
    __shared__ float Wm[300]; // w_ih @ l2_w : (30,10)
    int t = threadIdx.x;
    if (t < 300) {
        int r = t / 10, m = t % 10;
        float s = 0.0f;
        for (int i = 0; i < 64; i++) s += w_ih[r * 64 + i] * l2_w[i * 10 + m];
        Wm[t] = s;
    }
    __syncthreads();
    if (t < 300) {
        int r = t / 10, k = t % 10;
        float g = 0.0f;
        for (int m = 0; m < 10; m++) g += Wm[r * 10 + m] * l1_w[m * 10 + k];
        g_G[t] = g;
    } else if (t < 330) {
        int r = t - 300;
        float s = b_ih[r];
        for (int i = 0; i < 64; i++) s += w_ih[r * 64 + i] * l2_b[i];
        for (int m = 0; m < 10; m++) s += Wm[r * 10 + m] * l1_b[m];
        g_d[r] = s;
    }
}

// ---------- main recurrence kernel ----------
// thread = (duo, gate dim j); duo = 2 f32x2 pairs = 4 batch elements -> ILP=2
// independent streams through every latency segment. 3 duos per warp on lanes
// 0..29; lanes 30/31 shadow duo-slot 0 (identical stream, write smem slot 3 and
// sink). 740 warps, GRID=148 -> exactly 5 warps/SM, perfectly balanced.
// h exchanged via warp-local double-buffered shared rows (LDS.128), one
// __syncwarp per step. sigma(a)=0.5+0.5*tanh(a/2) with 0.5 folded into weights;
// all activations via tanh.approx.
__global__ void __launch_bounds__(TPB) gru_kernel(
    const float* __restrict__ hidden,
    const float* __restrict__ w_hh,
    const float* __restrict__ b_ih,
    const float* __restrict__ b_hh,
    const float* __restrict__ l1_w,
    const float* __restrict__ l1_b,
    float* __restrict__ out) {
    // [warp][buf][slot 0..3][pair 0..1][HID] ; slot 3 = spare-lane scratch
    __shared__ alignas(16) u64 hsh[WPB][2][4][2][HID];

    const int lane = threadIdx.x & 31;
    const int w    = threadIdx.x >> 5;
    const int p    = lane / 10;            // 0..2 duo slots, 3 = spare lanes
    const int dd   = (p < 3) ? p : 0;      // spares read slot 0
    const int j    = lane - p * 10;        // 0..9 (spares: 0..1)
    const int g    = blockIdx.x * WPB + w;
    const int duo  = g + dd * TOTW;
    const bool valid = (p < 3) && (duo < DUOS);
    const int e0   = valid ? duo * 4 : 0;  // 4 consecutive batch elements

    // per-thread folded + scaled weight rows, duplicated into both f32x2 halves
    u64 Mr[10], Mz[10], Gn[10], Wn[10], L1[10];
#pragma unroll
    for (int k = 0; k < 10; k++) {
        Mr[k] = fdup(0.5f * (w_hh[j * 10 + k]        + g_G[j * 10 + k]));
        Mz[k] = fdup(0.5f * (w_hh[(10 + j) * 10 + k] + g_G[(10 + j) * 10 + k]));
        Gn[k] = fdup(g_G[(20 + j) * 10 + k]);
        Wn[k] = fdup(w_hh[(20 + j) * 10 + k]);
        L1[k] = fdup(l1_w[j * 10 + k]);
    }
    const u64 vbr  = fdup(0.5f * (b_hh[j]      + g_d[j]));
    const u64 vbz  = fdup(0.5f * (b_hh[10 + j] + g_d[10 + j]));
    const u64 vbin = fdup(g_d[20 + j]);
    const u64 vbhn = fdup(b_hh[20 + j]);
    const u64 vl1b = fdup(l1_b[j]);
    const u64 ZERO2 = 0ULL;
    const u64 HALF2 = fdup(0.5f);
    const u64 NEG12 = fdup(-1.0f);

    u64 hvA = fpack(hidden[(e0 + 0) * 10 + j], hidden[(e0 + 1) * 10 + j]);
    u64 hvB = fpack(hidden[(e0 + 2) * 10 + j], hidden[(e0 + 3) * 10 + j]);

    hsh[w][0][p][0][j] = hvA;
    hsh[w][0][p][1][j] = hvB;
    __syncwarp();

    // peeled step 0: x0 = 0 -> gi = b_ih exactly. Exact activations (runs once).
    {
        const float bR0 = b_hh[j] + b_ih[j];
        const float bZ0 = b_hh[10 + j] + b_ih[10 + j];
        const float bH0 = b_hh[20 + j];
        const float bI0 = b_ih[20 + j];
#pragma unroll
        for (int pr = 0; pr < 2; pr++) {
            float hx, hy;
            funpack(pr == 0 ? hvA : hvB, hx, hy);
            float aRx = bR0, aRy = bR0, aZx = bZ0, aZy = bZ0, aHx = bH0, aHy = bH0;
#pragma unroll
            for (int k = 0; k < 10; k++) {
                float kx, ky;
                funpack(hsh[w][0][dd][pr][k], kx, ky);
                float wr = w_hh[j * 10 + k];
                float wz = w_hh[(10 + j) * 10 + k];
                float wn = w_hh[(20 + j) * 10 + k];
                aRx = fmaf(wr, kx, aRx); aRy = fmaf(wr, ky, aRy);
                aZx = fmaf(wz, kx, aZx); aZy = fmaf(wz, ky, aZy);
                aHx = fmaf(wn, kx, aHx); aHy = fmaf(wn, ky, aHy);
            }
            float rx = fsig_exact(aRx), ry = fsig_exact(aRy);
            float zx = fsig_exact(aZx), zy = fsig_exact(aZy);
            float nx = ftanh_exact(fmaf(rx, aHx, bI0));
            float ny = ftanh_exact(fmaf(ry, aHy, bI0));
            hx = fmaf(zx, hx - nx, nx);
            hy = fmaf(zy, hy - ny, ny);
            if (pr == 0) hvA = fpack(hx, hy); else hvB = fpack(hx, hy);
        }
    }
    hsh[w][1][p][0][j] = hvA;
    hsh[w][1][p][1][j] = hvB;

    // REVERSE output: o_t -> row (511 - t); at iter t we emit o_{t-1} -> row 512 - t.
    // invalid threads walk the sink with dec = 0 (branch-free, in-bounds).
    float *oA0, *oA1, *oB0, *oB1;
    int dec;
    if (valid) {
        float* base = out + (size_t)e0 * (STEPS * HID) + (size_t)(STEPS - 1) * HID + j;
        oA0 = base;
        oA1 = base + (size_t)STEPS * HID;
        oB0 = base + (size_t)2 * STEPS * HID;
        oB1 = base + (size_t)3 * STEPS * HID;
        dec = HID;
    } else {
        float* base = g_sink + ((g * 64 + p * 16) & 8191);
        oA0 = base + j; oA1 = base + j + 10; oB0 = base + j + 20; oB1 = base + j + 30;
        dec = 0;
    }

#pragma unroll 2
    for (int t = 1; t < STEPS; ++t) {
        __syncwarp();
        const int rb = t & 1;
        const ulonglong2* hpA = reinterpret_cast<const ulonglong2*>(&hsh[w][rb][dd][0][0]);
        const ulonglong2* hpB = reinterpret_cast<const ulonglong2*>(&hsh[w][rb][dd][1][0]);

        u64 aRA = vbr, aR2A = ZERO2, aHA = vbhn, aH2A = ZERO2;
        u64 aZA = vbz, aIA = vbin, aOA = vl1b;
        u64 aRB = vbr, aR2B = ZERO2, aHB = vbhn, aH2B = ZERO2;
        u64 aZB = vbz, aIB = vbin, aOB = vl1b;
#pragma unroll
        for (int kk = 0; kk < 5; kk++) {
            const ulonglong2 hA = hpA[kk];
            const ulonglong2 hB = hpB[kk];
            const int k = 2 * kk;
            aRA  = ffma2(Mr[k], hA.x, aRA);   aR2A = ffma2(Mr[k + 1], hA.y, aR2A);
            aRB  = ffma2(Mr[k], hB.x, aRB);   aR2B = ffma2(Mr[k + 1], hB.y, aR2B);
            aHA  = ffma2(Wn[k], hA.x, aHA);   aH2A = ffma2(Wn[k + 1], hA.y, aH2A);
            aHB  = ffma2(Wn[k], hB.x, aHB);   aH2B = ffma2(Wn[k + 1], hB.y, aH2B);
            aZA  = ffma2(Mz[k], hA.x, aZA);   aZA  = ffma2(Mz[k + 1], hA.y, aZA);
            aZB  = ffma2(Mz[k], hB.x, aZB);   aZB  = ffma2(Mz[k + 1], hB.y, aZB);
            aIA  = ffma2(Gn[k], hA.x, aIA);   aIA  = ffma2(Gn[k + 1], hA.y, aIA);
            aIB  = ffma2(Gn[k], hB.x, aIB);   aIB  = ffma2(Gn[k + 1], hB.y, aIB);
            aOA  = ffma2(L1[k], hA.x, aOA);   aOA  = ffma2(L1[k + 1], hA.y, aOA);
            aOB  = ffma2(L1[k], hB.x, aOB);   aOB  = ffma2(L1[k + 1], hB.y, aOB);
        }
        const u64 aRAm = fadd2(aRA, aR2A);
        const u64 aRBm = fadd2(aRB, aR2B);
        const u64 aHAm = fadd2(aHA, aH2A);
        const u64 aHBm = fadd2(aHB, aH2B);

        // store o_{t-1} (aO computed from h_t = h_new of step t-1)
        {
            float x, y;
            funpack(aOA, x, y); *oA0 = x; *oA1 = y;
            funpack(aOB, x, y); *oB0 = x; *oB1 = y;
            oA0 -= dec; oA1 -= dec; oB0 -= dec; oB1 -= dec;
        }

        // activations, pair A and B interleaved (independent chains)
        float rAx, rAy, zAx, zAy, rBx, rBy, zBx, zBy;
        funpack(aRAm, rAx, rAy); funpack(aRBm, rBx, rBy);
        funpack(aZA,  zAx, zAy); funpack(aZB,  zBx, zBy);
        const u64 rvA = ffma2(HALF2, fpack(ftanha(rAx), ftanha(rAy)), HALF2);
        const u64 rvB = ffma2(HALF2, fpack(ftanha(rBx), ftanha(rBy)), HALF2);
        const u64 zvA = ffma2(HALF2, fpack(ftanha(zAx), ftanha(zAy)), HALF2);
        const u64 zvB = ffma2(HALF2, fpack(ftanha(zBx), ftanha(zBy)), HALF2);

        const u64 argA = ffma2(rvA, aHAm, aIA);
        const u64 argB = ffma2(rvB, aHBm, aIB);
        float aAx, aAy, aBx, aBy;
        funpack(argA, aAx, aAy); funpack(argB, aBx, aBy);
        const u64 nvA = fpack(ftanha(aAx), ftanha(aAy));
        const u64 nvB = fpack(ftanha(aBx), ftanha(aBy));

        // h' = n + z*(h - n)
        hvA = ffma2(zvA, ffma2(nvA, NEG12, hvA), nvA);
        hvB = ffma2(zvB, ffma2(nvB, NEG12, hvB), nvB);
        hsh[w][rb ^ 1][p][0][j] = hvA;
        hsh[w][rb ^ 1][p][1][j] = hvB;
    }

    // epilogue: o_511 -> row 0 (h_512 sits in buffer 0 after t=511)
    __syncwarp();
    {
        u64 aOA = vl1b, aOB = vl1b;
#pragma unroll
        for (int k = 0; k < 10; k++) {
            aOA = ffma2(L1[k], hsh[w][0][dd][0][k], aOA);
            aOB = ffma2(L1[k], hsh[w][0][dd][1][k], aOB);
        }
        float x, y;
        funpack(aOA, x, y); *oA0 = x; *oA1 = y;
        funpack(aOB, x, y); *oB0 = x; *oB1 = y;
    }
}

extern "C" void kernel_launch(void* const* d_in, const int* in_sizes, int n_in,
                              void* d_out, int out_size) {
    const float* hidden = (const float*)d_in[0];
    const float* w_ih   = (const float*)d_in[1];
    const float* w_hh   = (const float*)d_in[2];
    const float* b_ih   = (const float*)d_in[3];
    const float* b_hh   = (const float*)d_in[4];
    const float* l1_w   = (const float*)d_in[5];
    const float* l1_b   = (const float*)d_in[6];
    const float* l2_w   = (const float*)d_in[7];
    const float* l2_b   = (const float*)d_in[8];

    prep_kernel<<<1, 384>>>(w_ih, b_ih, l1_w, l1_b, l2_w, l2_b);
    gru_kernel<<<GRID, TPB>>>(hidden, w_hh, b_ih, b_hh, l1_w, l1_b, (float*)d_out);
}